// round 5
// baseline (speedup 1.0000x reference)
#include <cuda_runtime.h>
#include <cstdint>

// ---------------------------------------------------------------------------
// SpatialWindowSelfAttention (Swin window MHSA), sm_103a — Round 3
//   1) TF32 GEMM (cp.async 2-stage pipeline)  qkv = x @ Wqkv^T + b
//   2) window attention, coalesced coop loads/stores
//   3) TF32 GEMM  out = y @ Wp^T + b
// ---------------------------------------------------------------------------

#define C_DIM    256
#define QKV_DIM  768
#define N_HEADS  8
#define HEAD_DIM 32
#define IMG      256
#define TOKENS   (IMG * IMG)
#define WS       64
#define MAX_B    2

__device__ float g_qkv[MAX_B * TOKENS * QKV_DIM];
__device__ float g_y  [MAX_B * TOKENS * C_DIM];

// ---------------------------------------------------------------------------
__device__ __forceinline__ uint32_t f2tf32(float x) {
    uint32_t r;
    asm("cvt.rna.tf32.f32 %0, %1;" : "=r"(r) : "f"(x));
    return r;
}

__device__ __forceinline__ void mma_tf32(float* d, const uint32_t* a, const uint32_t* b) {
    asm volatile(
        "mma.sync.aligned.m16n8k8.row.col.f32.tf32.tf32.f32 "
        "{%0,%1,%2,%3}, {%4,%5,%6,%7}, {%8,%9}, {%0,%1,%2,%3};\n"
        : "+f"(d[0]), "+f"(d[1]), "+f"(d[2]), "+f"(d[3])
        : "r"(a[0]), "r"(a[1]), "r"(a[2]), "r"(a[3]),
          "r"(b[0]), "r"(b[1]));
}

__device__ __forceinline__ void cp_async16(void* smem_dst, const void* gmem_src) {
    uint32_t s = (uint32_t)__cvta_generic_to_shared(smem_dst);
    asm volatile("cp.async.cg.shared.global [%0], [%1], 16;\n" :: "r"(s), "l"(gmem_src));
}
__device__ __forceinline__ void cp_commit() {
    asm volatile("cp.async.commit_group;\n");
}
template<int N>
__device__ __forceinline__ void cp_wait() {
    asm volatile("cp.async.wait_group %0;\n" :: "n"(N));
}

// ---------------------------------------------------------------------------
// TF32 GEMM: C[M,N] = A[M,K] @ Bw[N,K]^T + bias[N]
// BM=BN=128, BK=32, 256 threads (8 warps: 4 x M, 2 x N), warp tile 32x64.
// 2-stage cp.async pipeline; raw fp32 in smem, cvt.rna.tf32 at fragment read.
// Row stride 36 words (36 % 32 == 4): fragment banks = 4g+t -> conflict-free.
// ---------------------------------------------------------------------------
#define LDW 36
#define STAGE_WORDS (2 * 128 * LDW)   // A + B per stage = 9216 floats

__global__ __launch_bounds__(256)
void tf32_gemm_bias_kernel(const float* __restrict__ A,
                           const float* __restrict__ Bw,
                           const float* __restrict__ bias,
                           float* __restrict__ C,
                           int M, int N, int K)
{
    constexpr int BM = 128, BN = 128, BK = 32;
    extern __shared__ float smem[];

    const int tid  = threadIdx.x;
    const int lane = tid & 31;
    const int wid  = tid >> 5;
    const int wm   = (wid & 3) * 32;
    const int wn   = (wid >> 2) * 64;
    const int m0   = blockIdx.y * BM;
    const int n0   = blockIdx.x * BN;
    const int t    = lane & 3;
    const int g    = lane >> 2;

    // per-thread load slots: 4 float4 from A-tile, 4 from B-tile
    const int lrow = tid >> 3;        // rows 0..31 per i-chunk... (f>>3)
    (void)lrow;

    float acc[2][8][4];
    #pragma unroll
    for (int i = 0; i < 2; i++)
        #pragma unroll
        for (int j = 0; j < 8; j++)
            #pragma unroll
            for (int r = 0; r < 4; r++) acc[i][j][r] = 0.f;

    const int NT = K / BK;

    auto prefetch = [&](int kt, int s) {
        float* As = smem + s * STAGE_WORDS;
        float* Bs = As + 128 * LDW;
        const int k0 = kt * BK;
        #pragma unroll
        for (int i = 0; i < 4; i++) {
            int f   = tid + i * 256;
            int row = f >> 3;
            int kc  = (f & 7) * 4;
            cp_async16(As + row * LDW + kc,
                       A + (size_t)(m0 + row) * K + k0 + kc);
        }
        #pragma unroll
        for (int i = 0; i < 4; i++) {
            int f   = tid + i * 256;
            int row = f >> 3;
            int kc  = (f & 7) * 4;
            cp_async16(Bs + row * LDW + kc,
                       Bw + (size_t)(n0 + row) * K + k0 + kc);
        }
        cp_commit();
    };

    prefetch(0, 0);

    for (int kt = 0; kt < NT; kt++) {
        if (kt + 1 < NT) prefetch(kt + 1, (kt + 1) & 1);

        if (kt + 1 < NT) cp_wait<1>(); else cp_wait<0>();
        __syncthreads();

        const float* As = smem + (kt & 1) * STAGE_WORDS;
        const float* Bs = As + 128 * LDW;

        #pragma unroll
        for (int ks = 0; ks < 4; ks++) {
            const int kb = ks * 8;
            uint32_t a[2][4], b[8][2];
            #pragma unroll
            for (int mf = 0; mf < 2; mf++) {
                int r = wm + mf * 16 + g;
                a[mf][0] = f2tf32(As[(r    ) * LDW + kb + t    ]);
                a[mf][1] = f2tf32(As[(r + 8) * LDW + kb + t    ]);
                a[mf][2] = f2tf32(As[(r    ) * LDW + kb + t + 4]);
                a[mf][3] = f2tf32(As[(r + 8) * LDW + kb + t + 4]);
            }
            #pragma unroll
            for (int nf = 0; nf < 8; nf++) {
                int n = wn + nf * 8 + g;
                b[nf][0] = f2tf32(Bs[n * LDW + kb + t    ]);
                b[nf][1] = f2tf32(Bs[n * LDW + kb + t + 4]);
            }
            #pragma unroll
            for (int mf = 0; mf < 2; mf++)
                #pragma unroll
                for (int nf = 0; nf < 8; nf++)
                    mma_tf32(acc[mf][nf], a[mf], b[nf]);
        }
        __syncthreads();
    }

    #pragma unroll
    for (int mf = 0; mf < 2; mf++) {
        int row = m0 + wm + mf * 16 + g;
        #pragma unroll
        for (int nf = 0; nf < 8; nf++) {
            int col = n0 + wn + nf * 8 + 2 * t;
            float bx = bias[col], by = bias[col + 1];
            float2 v0 = make_float2(acc[mf][nf][0] + bx, acc[mf][nf][1] + by);
            float2 v1 = make_float2(acc[mf][nf][2] + bx, acc[mf][nf][3] + by);
            *(float2*)(C + (size_t)row * N + col)       = v0;
            *(float2*)(C + (size_t)(row + 8) * N + col) = v1;
        }
    }
}

// ---------------------------------------------------------------------------
// Window attention: block = (window, head), 64 threads.
// Cooperative coalesced loads: slot s -> token (s>>3), float4 (s&7);
// 8 consecutive threads fetch one token's 128B row segment.
// ---------------------------------------------------------------------------
__global__ __launch_bounds__(64)
void win_attn_kernel(const float* __restrict__ bias_table)
{
    __shared__ float Qs[WS][HEAD_DIM];
    __shared__ float Ks[WS][HEAD_DIM];
    __shared__ float Vs[WS][HEAD_DIM];
    __shared__ float bias_s[225];

    const int t    = threadIdx.x;
    const int head = blockIdx.y;
    const int bi   = blockIdx.x >> 10;
    const int wid  = blockIdx.x & 1023;
    const int wy   = wid >> 5, wx = wid & 31;

    // coalesced cooperative load of Q, K, V window tiles
    #pragma unroll
    for (int i = 0; i < 8; i++) {
        int slot = t + i * 64;          // 0..511
        int j    = slot >> 3;           // token in window
        int f    = slot & 7;            // float4 index within 32-float row
        int jr = j >> 3, jc = j & 7;
        size_t tok = (size_t)bi * TOKENS + (size_t)(wy * 8 + jr) * IMG + (wx * 8 + jc);
        const float4* base = (const float4*)(g_qkv + tok * QKV_DIM + head * HEAD_DIM);
        *(float4*)&Qs[j][f * 4] = base[f];
        *(float4*)&Ks[j][f * 4] = base[f + C_DIM / 4];
        *(float4*)&Vs[j][f * 4] = base[f + 2 * C_DIM / 4];
    }
    for (int i = t; i < 225; i += 64)
        bias_s[i] = bias_table[i * N_HEADS + head];
    __syncthreads();

    const int r = t >> 3, c = t & 7;

    float q[HEAD_DIM];
    #pragma unroll
    for (int d = 0; d < HEAD_DIM; d++) q[d] = Qs[t][d];

    const float scale = 0.17677669529663689f;   // 1/sqrt(32)
    float s[WS];
    #pragma unroll
    for (int k = 0; k < WS; k++) {
        float dot = 0.f;
        #pragma unroll
        for (int d = 0; d < HEAD_DIM; d++) dot += q[d] * Ks[k][d];
        int ki = k >> 3, kj = k & 7;
        s[k] = dot * scale + bias_s[(r - ki + 7) * 15 + (c - kj + 7)];
    }

    float m = -1e30f;
    #pragma unroll
    for (int k = 0; k < WS; k++) m = fmaxf(m, s[k]);
    float sum = 0.f;
    #pragma unroll
    for (int k = 0; k < WS; k++) { s[k] = __expf(s[k] - m); sum += s[k]; }
    const float inv = 1.f / sum;

    float y[HEAD_DIM];
    #pragma unroll
    for (int d = 0; d < HEAD_DIM; d++) y[d] = 0.f;
    #pragma unroll
    for (int k = 0; k < WS; k++) {
        float p = s[k];
        #pragma unroll
        for (int d = 0; d < HEAD_DIM; d++) y[d] += p * Vs[k][d];
    }

    // stage output in smem (reuse Qs), then coalesced cooperative store
    __syncthreads();
    #pragma unroll
    for (int d = 0; d < HEAD_DIM; d++) Qs[t][d] = y[d] * inv;
    __syncthreads();

    #pragma unroll
    for (int i = 0; i < 8; i++) {
        int slot = t + i * 64;
        int j    = slot >> 3;
        int f    = slot & 7;
        int jr = j >> 3, jc = j & 7;
        size_t tok = (size_t)bi * TOKENS + (size_t)(wy * 8 + jr) * IMG + (wx * 8 + jc);
        float4* dst = (float4*)(g_y + tok * C_DIM + head * HEAD_DIM);
        dst[f] = *(const float4*)&Qs[j][f * 4];
    }
}

// ---------------------------------------------------------------------------
extern "C" void kernel_launch(void* const* d_in, const int* in_sizes, int n_in,
                              void* d_out, int out_size)
{
    const float *x = nullptr, *wqkv_w = nullptr, *wqkv_b = nullptr;
    const float *wp_w = nullptr, *wp_b = nullptr, *bias_table = nullptr;
    long long x_elems = 0;
    for (int i = 0; i < n_in; i++) {
        long long sz = in_sizes[i];
        if      (sz == 768LL * 256)  wqkv_w = (const float*)d_in[i];
        else if (sz == 768)          wqkv_b = (const float*)d_in[i];
        else if (sz == 256LL * 256)  wp_w   = (const float*)d_in[i];
        else if (sz == 256)          wp_b   = (const float*)d_in[i];
        else if (sz == 225LL * 8)    bias_table = (const float*)d_in[i];
        else if (sz > 1000000)       { x = (const float*)d_in[i]; x_elems = sz; }
    }

    const int B = (int)(x_elems / ((long long)TOKENS * C_DIM));   // = 2
    const int M = B * TOKENS;

    float* qkv_ptr; cudaGetSymbolAddress((void**)&qkv_ptr, g_qkv);
    float* y_ptr;   cudaGetSymbolAddress((void**)&y_ptr,   g_y);

    const int smem_bytes = 2 * STAGE_WORDS * (int)sizeof(float);   // 73728
    static bool attr_set = false;
    if (!attr_set) {
        cudaFuncSetAttribute(tf32_gemm_bias_kernel,
                             cudaFuncAttributeMaxDynamicSharedMemorySize, smem_bytes);
        attr_set = true;
    }

    // 1) QKV projection
    {
        dim3 grid(QKV_DIM / 128, M / 128);
        tf32_gemm_bias_kernel<<<grid, 256, smem_bytes>>>(x, wqkv_w, wqkv_b, qkv_ptr,
                                                         M, QKV_DIM, C_DIM);
    }
    // 2) window attention
    {
        dim3 grid(B * 1024, N_HEADS);
        win_attn_kernel<<<grid, 64>>>(bias_table);
    }
    // 3) output projection
    {
        dim3 grid(C_DIM / 128, M / 128);
        tf32_gemm_bias_kernel<<<grid, 256, smem_bytes>>>(y_ptr, wp_w, wp_b, (float*)d_out,
                                                         M, C_DIM, C_DIM);
    }
}